// round 5
// baseline (speedup 1.0000x reference)
#include <cuda_runtime.h>
#include <cuda_fp16.h>

static constexpr int TOK   = 64;     // tokens per sequence
static constexpr int D     = 512;    // embedding dim
static constexpr int NC    = 64;     // classes
static constexpr int QN    = 2048;   // queries
static constexpr int SN    = 4096;   // supports
static constexpr int VOCAB = 32000;

// Scratch (allocation-free rule: __device__ globals)
__device__ __align__(16) __half g_table_h[VOCAB * D];  // fp16 shadow (32.8 MB)
__device__ float g_proto[NC * D];   // class sums, then normalized prototypes
__device__ float g_cnt[NC];         // per-class support counts
__device__ float g_p2[NC];          // ||proto||^2
__device__ float g_qemb[QN * D];    // query embeddings (mean-pooled)
__device__ float g_q2[QN];          // ||q||^2

// ---------------------------------------------------------------- kernel 1
__global__ void k_zero() {
    int i = blockIdx.x * blockDim.x + threadIdx.x;
    g_proto[i] = 0.0f;
    if (i < NC) g_cnt[i] = 0.0f;
}

// ---------------------------------------------------------------- kernel 2
// Convert embed table fp32 -> fp16 shadow. 8 elems/thread, 16B stores.
__global__ __launch_bounds__(256) void k_convert(const float* __restrict__ t)
{
    int i = blockIdx.x * blockDim.x + threadIdx.x;   // index of 8-elem group
    const float4* s = (const float4*)t;
    float4 a = s[2 * i];
    float4 b = s[2 * i + 1];
    __half2 h0 = __floats2half2_rn(a.x, a.y);
    __half2 h1 = __floats2half2_rn(a.z, a.w);
    __half2 h2 = __floats2half2_rn(b.x, b.y);
    __half2 h3 = __floats2half2_rn(b.z, b.w);
    uint4 o;
    o.x = *(const unsigned*)&h0;
    o.y = *(const unsigned*)&h1;
    o.z = *(const unsigned*)&h2;
    o.w = *(const unsigned*)&h3;
    ((uint4*)g_table_h)[i] = o;
}

// ---------------------------------------------------------------- kernel 3
// Unified gather: blocks [0, SN) = support rows, [SN, SN+QN) = query rows.
// 128 threads: dgrp = tid & 63 covers 8 halves (LDG.128); toff = tid >> 6
// picks odd/even tokens. 8 LDG.128 front-batched per loop -> 128 B/thread
// in flight for latency hiding.
__global__ __launch_bounds__(128) void k_gather(
    const int* __restrict__ q_toks,
    const int* __restrict__ s_toks,
    const int* __restrict__ labels)
{
    const bool is_sup = blockIdx.x < SN;
    const int  row    = is_sup ? blockIdx.x : blockIdx.x - SN;
    const int* toks   = is_sup ? s_toks : q_toks;

    __shared__ int sh_tok[TOK];
    __shared__ float sred[64 * 9];       // stride 9: conflict-free combine
    __shared__ float s_q2[2];            // per-warp q2 partials (toff==0 warps)

    if (threadIdx.x < TOK)
        sh_tok[threadIdx.x] = toks[(size_t)row * TOK + threadIdx.x];
    __syncthreads();

    const int dgrp = threadIdx.x & 63;   // which 8-half chunk of the row
    const int toff = threadIdx.x >> 6;   // 0 or 1: even/odd tokens

    float a[8];
    #pragma unroll
    for (int p = 0; p < 8; ++p) a[p] = 0.0f;

    // 32 tokens per half-block, in batches of 8 outstanding LDG.128.
    #pragma unroll
    for (int kb = 0; kb < 32; kb += 8) {
        uint4 v[8];
        #pragma unroll
        for (int u = 0; u < 8; ++u) {
            const int j = 2 * (kb + u) + toff;
            v[u] = *(const uint4*)(g_table_h + (size_t)sh_tok[j] * D + dgrp * 8);
        }
        #pragma unroll
        for (int u = 0; u < 8; ++u) {
            const __half2* h = (const __half2*)&v[u];
            #pragma unroll
            for (int p = 0; p < 4; ++p) {
                float2 f = __half22float2(h[p]);
                a[2 * p]     += f.x;
                a[2 * p + 1] += f.y;
            }
        }
    }

    // Combine the two token-halves (toff=1 -> smem, toff=0 adds).
    if (toff == 1) {
        #pragma unroll
        for (int p = 0; p < 8; ++p) sred[dgrp * 9 + p] = a[p];
    }
    __syncthreads();

    if (toff == 0) {
        const float s = 1.0f / (float)TOK;
        #pragma unroll
        for (int p = 0; p < 8; ++p) a[p] = (a[p] + sred[dgrp * 9 + p]) * s;

        if (is_sup) {
            const int c = labels[row];
            if (threadIdx.x == 0) atomicAdd(&g_cnt[c], 1.0f);
            float* dst = g_proto + c * D + dgrp * 8;
            #pragma unroll
            for (int p = 0; p < 8; ++p) atomicAdd(dst + p, a[p]);
        } else {
            float4* dst = (float4*)(g_qemb + (size_t)row * D) + dgrp * 2;
            dst[0] = make_float4(a[0], a[1], a[2], a[3]);
            dst[1] = make_float4(a[4], a[5], a[6], a[7]);

            float qq = 0.0f;
            #pragma unroll
            for (int p = 0; p < 8; ++p) qq += a[p] * a[p];
            #pragma unroll
            for (int o = 16; o > 0; o >>= 1)
                qq += __shfl_down_sync(0xFFFFFFFFu, qq, o);
            // toff==0 threads are warps 0 and 1
            if ((threadIdx.x & 31) == 0) s_q2[threadIdx.x >> 5] = qq;
        }
    }
    __syncthreads();
    if (!is_sup && threadIdx.x == 0)
        g_q2[row] = s_q2[0] + s_q2[1];
}

// ---------------------------------------------------------------- kernel 4
// One block per class: normalize proto by count, compute ||p||^2.
__global__ __launch_bounds__(128) void k_finalize()
{
    const int c = blockIdx.x;
    const float inv = 1.0f / fmaxf(g_cnt[c], 1.0f);

    float4* p = (float4*)(g_proto + c * D);
    float4 v = p[threadIdx.x];
    v.x *= inv; v.y *= inv; v.z *= inv; v.w *= inv;
    p[threadIdx.x] = v;

    float pp = v.x*v.x + v.y*v.y + v.z*v.z + v.w*v.w;
    #pragma unroll
    for (int o = 16; o > 0; o >>= 1) pp += __shfl_down_sync(0xFFFFFFFFu, pp, o);
    __shared__ float sp[4];
    if ((threadIdx.x & 31) == 0) sp[threadIdx.x >> 5] = pp;
    __syncthreads();
    if (threadIdx.x == 0) g_p2[c] = sp[0] + sp[1] + sp[2] + sp[3];
}

// ---------------------------------------------------------------- kernel 5
// 16 queries x 64 classes per block (256 threads, 4 outputs/thread).
__global__ __launch_bounds__(256) void k_out(float* __restrict__ out)
{
    const int c  = threadIdx.x & 63;
    const int g  = threadIdx.x >> 6;              // 0..3
    const int q0 = blockIdx.x * 16 + g * 4;

    const float4* pr = (const float4*)(g_proto + (size_t)c * D);
    const float4* qa = (const float4*)(g_qemb + (size_t)(q0 + 0) * D);
    const float4* qb = (const float4*)(g_qemb + (size_t)(q0 + 1) * D);
    const float4* qc = (const float4*)(g_qemb + (size_t)(q0 + 2) * D);
    const float4* qd = (const float4*)(g_qemb + (size_t)(q0 + 3) * D);

    float d0 = 0.f, d1 = 0.f, d2 = 0.f, d3 = 0.f;
    #pragma unroll 4
    for (int i = 0; i < D / 4; ++i) {
        float4 p = pr[i];
        float4 a = qa[i], b = qb[i], x = qc[i], y = qd[i];
        d0 += p.x*a.x + p.y*a.y + p.z*a.z + p.w*a.w;
        d1 += p.x*b.x + p.y*b.y + p.z*b.z + p.w*b.w;
        d2 += p.x*x.x + p.y*x.y + p.z*x.z + p.w*x.w;
        d3 += p.x*y.x + p.y*y.y + p.z*y.z + p.w*y.w;
    }
    const float p2 = g_p2[c];
    out[(size_t)(q0 + 0) * NC + c] = -(g_q2[q0 + 0] + p2 - 2.0f * d0);
    out[(size_t)(q0 + 1) * NC + c] = -(g_q2[q0 + 1] + p2 - 2.0f * d1);
    out[(size_t)(q0 + 2) * NC + c] = -(g_q2[q0 + 2] + p2 - 2.0f * d2);
    out[(size_t)(q0 + 3) * NC + c] = -(g_q2[q0 + 3] + p2 - 2.0f * d3);
}

// ----------------------------------------------------------------
extern "C" void kernel_launch(void* const* d_in, const int* in_sizes, int n_in,
                              void* d_out, int out_size)
{
    // JAX x64 disabled -> "int64" tensors are int32 on the wire.
    const int*   query   = (const int*)d_in[0];
    const int*   support = (const int*)d_in[1];
    const int*   labels  = (const int*)d_in[2];
    const float* table   = (const float*)d_in[3];
    float* out = (float*)d_out;

    k_zero<<<NC, D>>>();
    k_convert<<<(VOCAB * D / 8) / 256, 256>>>(table);     // fp32 -> fp16 shadow
    k_gather<<<SN + QN, 128>>>(query, support, labels);   // all gathers, one wave
    k_finalize<<<NC, 128>>>();
    k_out<<<QN / 16, 256>>>(out);
}

// round 6
// speedup vs baseline: 1.0540x; 1.0540x over previous
#include <cuda_runtime.h>
#include <cuda_fp16.h>

static constexpr int TOK   = 64;     // tokens per sequence
static constexpr int D     = 512;    // embedding dim
static constexpr int NC    = 64;     // classes
static constexpr int QN    = 2048;   // queries
static constexpr int SN    = 4096;   // supports
static constexpr int VOCAB = 32000;

// Scratch (allocation-free rule: __device__ globals)
__device__ __align__(16) __half g_table_h[VOCAB * D];  // fp16 shadow (32.8 MB)
__device__ float g_proto[NC * D];   // RAW class sums (never normalized)
__device__ float g_cnt[NC];         // per-class support counts
__device__ float g_qemb[QN * D];    // query embeddings (mean-pooled)
__device__ float g_q2[QN];          // ||q||^2

// ---------------------------------------------------------------- kernel 1
// Convert embed table fp32 -> fp16 shadow (8 elems/thread, 16B stores).
// Also zeroes the proto-sum / count scratch: the 2.048M threads of this grid
// exactly cover the 32768-float proto array and 64 counts.
__global__ __launch_bounds__(256) void k_convert(const float* __restrict__ t)
{
    const int i = blockIdx.x * blockDim.x + threadIdx.x;  // 8-elem group id
    if (i < NC * D) g_proto[i] = 0.0f;
    if (i < NC)     g_cnt[i]   = 0.0f;

    const float4* s = (const float4*)t;
    float4 a = s[2 * i];
    float4 b = s[2 * i + 1];
    __half2 h0 = __floats2half2_rn(a.x, a.y);
    __half2 h1 = __floats2half2_rn(a.z, a.w);
    __half2 h2 = __floats2half2_rn(b.x, b.y);
    __half2 h3 = __floats2half2_rn(b.z, b.w);
    uint4 o;
    o.x = *(const unsigned*)&h0;
    o.y = *(const unsigned*)&h1;
    o.z = *(const unsigned*)&h2;
    o.w = *(const unsigned*)&h3;
    ((uint4*)g_table_h)[i] = o;
}

// ---------------------------------------------------------------- kernel 2
// Unified gather, R3-proven inner loop: blocks [0, SN) = support rows,
// [SN, SN+QN) = query rows. 128 threads; thread t owns dims [4t, 4t+4)
// via one uint2 (4 halves) per token; 64 serially-unrolled token loads.
__global__ __launch_bounds__(128) void k_gather(
    const int* __restrict__ q_toks,
    const int* __restrict__ s_toks,
    const int* __restrict__ labels)
{
    const bool is_sup = blockIdx.x < SN;
    const int  row    = is_sup ? blockIdx.x : blockIdx.x - SN;
    const int* toks   = is_sup ? s_toks : q_toks;

    __shared__ int sh_tok[TOK];
    if (threadIdx.x < TOK)
        sh_tok[threadIdx.x] = toks[(size_t)row * TOK + threadIdx.x];
    __syncthreads();

    float a0 = 0.f, a1 = 0.f, a2 = 0.f, a3 = 0.f;
    #pragma unroll 8
    for (int j = 0; j < TOK; ++j) {
        const uint2* r = (const uint2*)(g_table_h + (size_t)sh_tok[j] * D);
        uint2 v = r[threadIdx.x];                        // 4 halves
        float2 f0 = __half22float2(*(const __half2*)&v.x);
        float2 f1 = __half22float2(*(const __half2*)&v.y);
        a0 += f0.x; a1 += f0.y; a2 += f1.x; a3 += f1.y;
    }
    const float s = 1.0f / (float)TOK;
    a0 *= s; a1 *= s; a2 *= s; a3 *= s;

    if (is_sup) {
        const int c = labels[row];
        if (threadIdx.x == 0) atomicAdd(&g_cnt[c], 1.0f);
        float* dst = g_proto + c * D + threadIdx.x * 4;
        atomicAdd(dst + 0, a0);
        atomicAdd(dst + 1, a1);
        atomicAdd(dst + 2, a2);
        atomicAdd(dst + 3, a3);
    } else {
        ((float4*)(g_qemb + (size_t)row * D))[threadIdx.x] =
            make_float4(a0, a1, a2, a3);

        float qq = a0*a0 + a1*a1 + a2*a2 + a3*a3;
        #pragma unroll
        for (int o = 16; o > 0; o >>= 1)
            qq += __shfl_down_sync(0xFFFFFFFFu, qq, o);
        __shared__ float sp[4];
        if ((threadIdx.x & 31) == 0) sp[threadIdx.x >> 5] = qq;
        __syncthreads();
        if (threadIdx.x == 0) g_q2[row] = sp[0] + sp[1] + sp[2] + sp[3];
    }
}

// ---------------------------------------------------------------- kernel 3
// 16 queries x 64 classes per block (256 threads, 4 outputs/thread).
// Works on RAW proto sums: normalization + ||p||^2 folded in
// (p = inv*raw  =>  p2 = inv^2 * sum(raw^2),  q.p = inv * (q.raw)).
__global__ __launch_bounds__(256) void k_out(float* __restrict__ out)
{
    const int c  = threadIdx.x & 63;
    const int g  = threadIdx.x >> 6;              // 0..3
    const int q0 = blockIdx.x * 16 + g * 4;

    const float4* pr = (const float4*)(g_proto + (size_t)c * D);
    const float4* qa = (const float4*)(g_qemb + (size_t)(q0 + 0) * D);
    const float4* qb = (const float4*)(g_qemb + (size_t)(q0 + 1) * D);
    const float4* qc = (const float4*)(g_qemb + (size_t)(q0 + 2) * D);
    const float4* qd = (const float4*)(g_qemb + (size_t)(q0 + 3) * D);

    float d0 = 0.f, d1 = 0.f, d2 = 0.f, d3 = 0.f, pp = 0.f;
    #pragma unroll 4
    for (int i = 0; i < D / 4; ++i) {
        float4 p = pr[i];
        float4 a = qa[i], b = qb[i], x = qc[i], y = qd[i];
        pp += p.x*p.x + p.y*p.y + p.z*p.z + p.w*p.w;
        d0 += p.x*a.x + p.y*a.y + p.z*a.z + p.w*a.w;
        d1 += p.x*b.x + p.y*b.y + p.z*b.z + p.w*b.w;
        d2 += p.x*x.x + p.y*x.y + p.z*x.z + p.w*x.w;
        d3 += p.x*y.x + p.y*y.y + p.z*y.z + p.w*y.w;
    }
    const float inv  = 1.0f / fmaxf(g_cnt[c], 1.0f);
    const float p2   = pp * inv * inv;
    const float two_inv = 2.0f * inv;
    out[(size_t)(q0 + 0) * NC + c] = -(g_q2[q0 + 0] + p2 - two_inv * d0);
    out[(size_t)(q0 + 1) * NC + c] = -(g_q2[q0 + 1] + p2 - two_inv * d1);
    out[(size_t)(q0 + 2) * NC + c] = -(g_q2[q0 + 2] + p2 - two_inv * d2);
    out[(size_t)(q0 + 3) * NC + c] = -(g_q2[q0 + 3] + p2 - two_inv * d3);
}

// ----------------------------------------------------------------
extern "C" void kernel_launch(void* const* d_in, const int* in_sizes, int n_in,
                              void* d_out, int out_size)
{
    // JAX x64 disabled -> "int64" tensors are int32 on the wire.
    const int*   query   = (const int*)d_in[0];
    const int*   support = (const int*)d_in[1];
    const int*   labels  = (const int*)d_in[2];
    const float* table   = (const float*)d_in[3];
    float* out = (float*)d_out;

    k_convert<<<(VOCAB * D / 8) / 256, 256>>>(table);     // convert + zero scratch
    k_gather<<<SN + QN, 128>>>(query, support, labels);   // all gathers, one wave
    k_out<<<QN / 16, 256>>>(out);                         // distances (+finalize)
}